// round 1
// baseline (speedup 1.0000x reference)
#include <cuda_runtime.h>

#define BATCH 16
#define SEQ 256
#define DIM 256
#define MAT (SEQ*DIM)          // 65536
#define NTOT (BATCH*MAT)       // 1048576

// Scratch (device globals: no allocation allowed)
__device__ float g_attn[NTOT];
__device__ float g_x1att[NTOT];
__device__ float g_x2att[NTOT];
__device__ float g_n1[BATCH*SEQ];
__device__ float g_n2[BATCH*SEQ];
// channel stats: 0=x1, 1=x1_att, 2=x2, 3=x2_att
__device__ float g_sum[4];
__device__ float g_sumsq[4];

// ---------------------------------------------------------------------------
// K_zero: reset stat accumulators (needed every graph replay)
// ---------------------------------------------------------------------------
__global__ void k_zero() {
    int t = threadIdx.x;
    if (t < 4) { g_sum[t] = 0.f; g_sumsq[t] = 0.f; }
}

// ---------------------------------------------------------------------------
// K_norms: row sumsq (norms) of x1/x2 + channel-0/2 BN stats
// grid: 1024 blocks x 256 threads. blocks [0,512) -> x1, [512,1024) -> x2.
// one warp per row of 256 floats.
// ---------------------------------------------------------------------------
__global__ void __launch_bounds__(256) k_norms(const float* __restrict__ x1,
                                               const float* __restrict__ x2) {
    int blk = blockIdx.x;
    const float* X;
    float* Nrm;
    int ch;
    if (blk < 512) { X = x1; Nrm = g_n1; ch = 0; }
    else           { X = x2; Nrm = g_n2; blk -= 512; ch = 2; }
    int warp = threadIdx.x >> 5, lane = threadIdx.x & 31;
    int row = blk * 8 + warp;               // 0..4095 = b*SEQ + s
    const float* p = X + row * DIM;
    float s = 0.f, q = 0.f;
#pragma unroll
    for (int c = 0; c < 8; c++) {
        float v = p[lane + c * 32];
        s += v; q += v * v;
    }
#pragma unroll
    for (int off = 16; off; off >>= 1) {
        s += __shfl_xor_sync(0xffffffffu, s, off);
        q += __shfl_xor_sync(0xffffffffu, q, off);
    }
    __shared__ float bs[8], bq[8];
    if (lane == 0) { Nrm[row] = q; bs[warp] = s; bq[warp] = q; }
    __syncthreads();
    if (threadIdx.x == 0) {
        float S = 0.f, Q = 0.f;
#pragma unroll
        for (int w = 0; w < 8; w++) { S += bs[w]; Q += bq[w]; }
        atomicAdd(&g_sum[ch], S);
        atomicAdd(&g_sumsq[ch], Q);
    }
}

// ---------------------------------------------------------------------------
// K_attn: per-batch 256x256 pairwise attention via GEMM expansion.
// attn[b][j][i] = 1/(sqrt(max(n1[i]+n2[j]-2*dot,0)+1e-6)+1)
// 64x64 tile, 16x16 threads, 4x4 micro-tile, K chunks of 16.
// grid (4,4,16): x -> i-tile, y -> j-tile, z -> batch
// ---------------------------------------------------------------------------
__global__ void __launch_bounds__(256) k_attn(const float* __restrict__ x1,
                                              const float* __restrict__ x2) {
    __shared__ float s1[16][68];   // [kk][i]  from x1
    __shared__ float s2[16][68];   // [kk][j]  from x2
    __shared__ float sn1[64], sn2[64];
    int b = blockIdx.z;
    int i0 = blockIdx.x * 64, j0 = blockIdx.y * 64;
    int t = threadIdx.x;
    int tx = t & 15, ty = t >> 4;
    const float* X1 = x1 + b * MAT;
    const float* X2 = x2 + b * MAT;
    if (t < 64)       sn1[t]      = g_n1[b * SEQ + i0 + t];
    else if (t < 128) sn2[t - 64] = g_n2[b * SEQ + j0 + (t - 64)];
    int lr = t >> 2, ls = (t & 3) << 2;
    float acc[4][4] = {};
    for (int k0 = 0; k0 < DIM; k0 += 16) {
        float4 v1 = *(const float4*)&X1[(i0 + lr) * DIM + k0 + ls];
        float4 v2 = *(const float4*)&X2[(j0 + lr) * DIM + k0 + ls];
        __syncthreads();
        s1[ls + 0][lr] = v1.x; s1[ls + 1][lr] = v1.y; s1[ls + 2][lr] = v1.z; s1[ls + 3][lr] = v1.w;
        s2[ls + 0][lr] = v2.x; s2[ls + 1][lr] = v2.y; s2[ls + 2][lr] = v2.z; s2[ls + 3][lr] = v2.w;
        __syncthreads();
#pragma unroll
        for (int kk = 0; kk < 16; kk++) {
            float4 av = *(const float4*)&s2[kk][ty << 2];
            float4 bv = *(const float4*)&s1[kk][tx << 2];
            float a[4] = { av.x, av.y, av.z, av.w };
            float w[4] = { bv.x, bv.y, bv.z, bv.w };
#pragma unroll
            for (int m = 0; m < 4; m++)
#pragma unroll
                for (int n = 0; n < 4; n++)
                    acc[m][n] += a[m] * w[n];
        }
    }
#pragma unroll
    for (int m = 0; m < 4; m++) {
        int j = j0 + (ty << 2) + m;
        float n2v = sn2[(ty << 2) + m];
#pragma unroll
        for (int n = 0; n < 4; n++) {
            int i = i0 + (tx << 2) + n;
            float d2 = fmaxf(sn1[(tx << 2) + n] + n2v - 2.f * acc[m][n], 0.f);
            g_attn[b * MAT + j * DIM + i] = 1.f / (sqrtf(d2 + 1e-6f) + 1.f);
        }
    }
}

// ---------------------------------------------------------------------------
// K_attgemm: both attention projections.
// which=0: x2_att[b][j][o] = sum_i attn[b][j][i] * W[o][i] + bias[o]   (ch 3)
// which=1: x1_att[b][i][o] = sum_j attn[b][j][i] * W[o][j] + bias[o]   (ch 1)
// grid (4,4,32): x -> o-tile, y -> r-tile, z = b*2 + which
// Epilogue accumulates BN channel stats via block reduce + 2 atomics.
// ---------------------------------------------------------------------------
__global__ void __launch_bounds__(256) k_attgemm(const float* __restrict__ W,
                                                 const float* __restrict__ bias) {
    __shared__ float sa[16][68];   // [kk][r]
    __shared__ float sw[16][68];   // [kk][o]
    __shared__ float sbias[64];
    int bz = blockIdx.z;
    int b = bz >> 1, which = bz & 1;
    int o0 = blockIdx.x * 64, r0 = blockIdx.y * 64;
    const float* A = g_attn + b * MAT;
    int t = threadIdx.x, tx = t & 15, ty = t >> 4;
    int lr = t >> 2, ls = (t & 3) << 2;
    if (t < 64) sbias[t] = bias[o0 + t];
    float acc[4][4] = {};
    for (int k0 = 0; k0 < SEQ; k0 += 16) {
        float4 wv = *(const float4*)&W[(o0 + lr) * SEQ + k0 + ls];
        float4 av;
        if (which == 0) av = *(const float4*)&A[(r0 + lr) * DIM + k0 + ls];
        else            av = *(const float4*)&A[(k0 + ty) * DIM + r0 + (tx << 2)];
        __syncthreads();
        sw[ls + 0][lr] = wv.x; sw[ls + 1][lr] = wv.y; sw[ls + 2][lr] = wv.z; sw[ls + 3][lr] = wv.w;
        if (which == 0) {
            sa[ls + 0][lr] = av.x; sa[ls + 1][lr] = av.y; sa[ls + 2][lr] = av.z; sa[ls + 3][lr] = av.w;
        } else {
            *(float4*)&sa[ty][tx << 2] = av;   // row base 272B (16B-aligned), col mult of 4
        }
        __syncthreads();
#pragma unroll
        for (int kk = 0; kk < 16; kk++) {
            float4 a4 = *(const float4*)&sa[kk][ty << 2];
            float4 w4 = *(const float4*)&sw[kk][tx << 2];
            float a[4] = { a4.x, a4.y, a4.z, a4.w };
            float w[4] = { w4.x, w4.y, w4.z, w4.w };
#pragma unroll
            for (int m = 0; m < 4; m++)
#pragma unroll
                for (int n = 0; n < 4; n++)
                    acc[m][n] += a[m] * w[n];
        }
    }
    float* out = which ? g_x1att : g_x2att;
    float ps = 0.f, pq = 0.f;
#pragma unroll
    for (int m = 0; m < 4; m++) {
        int r = r0 + (ty << 2) + m;
#pragma unroll
        for (int n = 0; n < 4; n++) {
            int o = o0 + (tx << 2) + n;
            float v = acc[m][n] + sbias[(tx << 2) + n];
            out[b * MAT + r * DIM + o] = v;
            ps += v; pq += v * v;
        }
    }
    __shared__ float rs[256], rq[256];
    rs[t] = ps; rq[t] = pq;
    __syncthreads();
    for (int off = 128; off; off >>= 1) {
        if (t < off) { rs[t] += rs[t + off]; rq[t] += rq[t + off]; }
        __syncthreads();
    }
    if (t == 0) {
        int ch = which ? 1 : 3;
        atomicAdd(&g_sum[ch], rs[0]);
        atomicAdd(&g_sumsq[ch], rq[0]);
    }
}

// ---------------------------------------------------------------------------
// K_bn: apply training-mode BN and write both outputs.
// out layout: [which_out(2)][b(16)][c(2)][s(256)][d(256)]
// grid 4096 x 256, one float4 per thread (4M elements total)
// ---------------------------------------------------------------------------
__global__ void __launch_bounds__(256) k_bn(const float* __restrict__ x1,
                                            const float* __restrict__ x2,
                                            const float* __restrict__ gamma,
                                            const float* __restrict__ beta,
                                            float* __restrict__ out) {
    int idx = blockIdx.x * blockDim.x + threadIdx.x;  // float4 index
    int e = idx << 2;                                  // element index
    int which = e >> 21;
    int rem = e & ((1 << 21) - 1);
    int bb = rem >> 17;
    int c = (rem >> 16) & 1;
    int pos = rem & 65535;
    const float* src;
    int ch;
    if (which == 0) { src = c ? g_x1att : x1; ch = c ? 1 : 0; }
    else            { src = c ? g_x2att : x2; ch = c ? 3 : 2; }
    const float Ninv = 1.0f / (float)NTOT;
    float mean = g_sum[ch] * Ninv;
    float var = g_sumsq[ch] * Ninv - mean * mean;
    float sc = gamma[c] * rsqrtf(var + 1e-5f);
    float sh = beta[c] - mean * sc;
    float4 v = *(const float4*)&src[bb * MAT + pos];
    float4 o;
    o.x = v.x * sc + sh;
    o.y = v.y * sc + sh;
    o.z = v.z * sc + sh;
    o.w = v.w * sc + sh;
    *(float4*)&out[e] = o;
}

// ---------------------------------------------------------------------------
extern "C" void kernel_launch(void* const* d_in, const int* in_sizes, int n_in,
                              void* d_out, int out_size) {
    const float* x1    = (const float*)d_in[0];
    const float* x2    = (const float*)d_in[1];
    const float* W     = (const float*)d_in[2];
    const float* bias  = (const float*)d_in[3];
    const float* gamma = (const float*)d_in[4];
    const float* beta  = (const float*)d_in[5];
    float* out = (float*)d_out;

    k_zero<<<1, 32>>>();
    k_norms<<<1024, 256>>>(x1, x2);
    k_attn<<<dim3(4, 4, 16), 256>>>(x1, x2);
    k_attgemm<<<dim3(4, 4, 32), 256>>>(W, bias);
    k_bn<<<4096, 256>>>(x1, x2, gamma, beta, out);
}

// round 3
// speedup vs baseline: 1.7255x; 1.7255x over previous
#include <cuda_runtime.h>
#include <cuda_bf16.h>
#include <stdint.h>

#define BATCH 16
#define SEQ 256
#define DIM 256
#define MAT 65536
#define NTOT 1048576

// ---------------------------------------------------------------------------
// Device-global scratch (no allocation allowed)
// ---------------------------------------------------------------------------
__device__ float g_x1att[NTOT];
__device__ float g_x2att[NTOT];
__device__ float g_n1[BATCH*SEQ];
__device__ float g_n2[BATCH*SEQ];
__device__ float g_sum[4];     // 0=x1, 1=x1_att, 2=x2, 3=x2_att
__device__ float g_sumsq[4];
__device__ __nv_bfloat16 g_x1b[NTOT];
__device__ __nv_bfloat16 g_x2b[NTOT];
__device__ __nv_bfloat16 g_Whi[SEQ*DIM];
__device__ __nv_bfloat16 g_Wlo[SEQ*DIM];
__device__ __nv_bfloat16 g_attn_hi[NTOT];   // [b][j][i]
__device__ __nv_bfloat16 g_attn_lo[NTOT];
__device__ __nv_bfloat16 g_attnT_hi[NTOT];  // [b][i][j]
__device__ __nv_bfloat16 g_attnT_lo[NTOT];

// ---------------------------------------------------------------------------
// Portable-ISA helpers (sm_80+): ldmatrix / mma.sync bf16 / cp.async
// ---------------------------------------------------------------------------
__device__ __forceinline__ uint32_t smem_to_u32(const void* p) {
    uint32_t a;
    asm("{ .reg .u64 t; cvta.to.shared.u64 t, %1; cvt.u32.u64 %0, t; }" : "=r"(a) : "l"(p));
    return a;
}
__device__ __forceinline__ void ldsm4(uint32_t* r, uint32_t addr) {
    asm volatile("ldmatrix.sync.aligned.m8n8.x4.shared.b16 {%0,%1,%2,%3}, [%4];"
                 : "=r"(r[0]), "=r"(r[1]), "=r"(r[2]), "=r"(r[3]) : "r"(addr));
}
__device__ __forceinline__ void mma_bf16(float* c, const uint32_t* a, const uint32_t* b) {
    asm volatile("mma.sync.aligned.m16n8k16.row.col.f32.bf16.bf16.f32 "
                 "{%0,%1,%2,%3}, {%4,%5,%6,%7}, {%8,%9}, {%0,%1,%2,%3};"
                 : "+f"(c[0]), "+f"(c[1]), "+f"(c[2]), "+f"(c[3])
                 : "r"(a[0]), "r"(a[1]), "r"(a[2]), "r"(a[3]), "r"(b[0]), "r"(b[1]));
}
__device__ __forceinline__ void cp16(uint32_t saddr, const void* g) {
    asm volatile("cp.async.cg.shared.global [%0], [%1], 16;" :: "r"(saddr), "l"(g));
}
#define CP_COMMIT() asm volatile("cp.async.commit_group;" ::: "memory")
#define CP_WAIT1()  asm volatile("cp.async.wait_group 1;" ::: "memory")
#define CP_WAIT0()  asm volatile("cp.async.wait_group 0;" ::: "memory")

// SMEM tile geometry: rows of 64 bf16 (one K-chunk) padded to 72 halves (144B)
#define TROW 144                 // bytes per row
#define TILE_B (128 * TROW)      // 18432 bytes per tile buffer

// ---------------------------------------------------------------------------
// k_zero
// ---------------------------------------------------------------------------
__global__ void k_zero() {
    int t = threadIdx.x;
    if (t < 4) { g_sum[t] = 0.f; g_sumsq[t] = 0.f; }
}

// ---------------------------------------------------------------------------
// k_prep: row norms + ch0/2 BN stats + bf16 conversions + W hi/lo split
// blocks [0,512): x1   [512,1024): x2   [1024,1088): W
// ---------------------------------------------------------------------------
__global__ void __launch_bounds__(256) k_prep(const float* __restrict__ x1,
                                              const float* __restrict__ x2,
                                              const float* __restrict__ W) {
    int blk = blockIdx.x;
    int t = threadIdx.x;
    if (blk >= 1024) {
        int base = (blk - 1024) * 1024;
#pragma unroll
        for (int c = 0; c < 4; c++) {
            int i = base + c * 256 + t;
            float w = W[i];
            __nv_bfloat16 h = __float2bfloat16(w);
            g_Whi[i] = h;
            g_Wlo[i] = __float2bfloat16(w - __bfloat162float(h));
        }
        return;
    }
    const float* X;
    float* Nrm;
    __nv_bfloat16* Xb;
    int ch;
    if (blk < 512) { X = x1; Nrm = g_n1; Xb = g_x1b; ch = 0; }
    else           { X = x2; Nrm = g_n2; Xb = g_x2b; blk -= 512; ch = 2; }
    int warp = t >> 5, lane = t & 31;
    int row = blk * 8 + warp;
    const float* p = X + row * DIM;
    __nv_bfloat16* pb = Xb + row * DIM;
    float s = 0.f, q = 0.f;
#pragma unroll
    for (int c = 0; c < 8; c++) {
        float v = p[lane + c * 32];
        s += v; q += v * v;
        pb[lane + c * 32] = __float2bfloat16(v);
    }
#pragma unroll
    for (int off = 16; off; off >>= 1) {
        s += __shfl_xor_sync(0xffffffffu, s, off);
        q += __shfl_xor_sync(0xffffffffu, q, off);
    }
    __shared__ float bs[8], bq[8];
    if (lane == 0) { Nrm[row] = q; bs[warp] = s; bq[warp] = q; }
    __syncthreads();
    if (t == 0) {
        float S = 0.f, Q = 0.f;
#pragma unroll
        for (int w = 0; w < 8; w++) { S += bs[w]; Q += bq[w]; }
        atomicAdd(&g_sum[ch], S);
        atomicAdd(&g_sumsq[ch], Q);
    }
}

// ---------------------------------------------------------------------------
// k_gemm1: HMMA bf16  D[i][j] = x1_i . x2_j  (128x128 CTA tile, K=256)
// epilogue: attn = 1/(sqrt(max(n1+n2-2D,0)+1e-6)+1), emitted hi/lo bf16 in
// both layouts via SMEM staging.
// grid (2,2,16), 256 threads, 8 warps of 64x32.
// SMEM: [0,512) n1  [512,1024) n2  [1024, +4*TILE_B) A/B double buffers
//       epilogue: th at 1024 (128x136 ushort), tl at 1024+34816
// ---------------------------------------------------------------------------
#define G1_SMEM (1024 + 4 * TILE_B)   // 74752

__global__ void __launch_bounds__(256) k_gemm1() {
    extern __shared__ char smem[];
    uint32_t sb = smem_to_u32(smem);
    float* sn1 = (float*)smem;
    float* sn2 = (float*)(smem + 512);
    int t = threadIdx.x, lane = t & 31, wid = t >> 5;
    int b = blockIdx.z, i0 = blockIdx.x * 128, j0 = blockIdx.y * 128;
    int m0w = (wid & 1) * 64, n0w = (wid >> 1) * 32;

    const __nv_bfloat16* A = g_x1b + b * MAT + i0 * DIM;
    const __nv_bfloat16* B = g_x2b + b * MAT + j0 * DIM;
    if (t < 128) sn1[t] = g_n1[b * SEQ + i0 + t];
    else         sn2[t - 128] = g_n2[b * SEQ + j0 + (t - 128)];

    const uint32_t sA = sb + 1024;
    const uint32_t sB = sb + 1024 + 2 * TILE_B;

    // chunk loader: 64-wide K slab of A and B into buffer `buf`
    auto load_chunk = [&](int kc, int buf) {
#pragma unroll
        for (int s = 0; s < 4; s++) {
            int seg = t + s * 256;
            int row = seg >> 3, c = seg & 7;
            uint32_t so = (uint32_t)(buf * TILE_B + row * TROW + c * 16);
            const __nv_bfloat16* ga = A + row * DIM + kc * 64 + c * 8;
            const __nv_bfloat16* gb = B + row * DIM + kc * 64 + c * 8;
            cp16(sA + so, ga);
            cp16(sB + so, gb);
        }
    };

    float acc[4][4][4] = {};
    load_chunk(0, 0);
    CP_COMMIT();
    for (int kc = 0; kc < 4; kc++) {
        if (kc + 1 < 4) { load_chunk(kc + 1, (kc + 1) & 1); }
        CP_COMMIT();
        if (kc + 1 < 4) CP_WAIT1(); else CP_WAIT0();
        __syncthreads();
        uint32_t bufA = sA + (kc & 1) * TILE_B;
        uint32_t bufB = sB + (kc & 1) * TILE_B;
#pragma unroll
        for (int kk = 0; kk < 4; kk++) {
            uint32_t af[4][4];
#pragma unroll
            for (int mi = 0; mi < 4; mi++) {
                uint32_t addr = bufA + (uint32_t)((m0w + mi * 16 + (lane & 15)) * TROW
                                                  + kk * 32 + (lane >> 4) * 16);
                ldsm4(af[mi], addr);
            }
            uint32_t bf[4][2];
#pragma unroll
            for (int np = 0; np < 2; np++) {
                uint32_t r[4];
                uint32_t addr = bufB + (uint32_t)((n0w + np * 16 + (lane & 7) + ((lane >> 4) & 1) * 8) * TROW
                                                  + kk * 32 + ((lane >> 3) & 1) * 16);
                ldsm4(r, addr);
                bf[np * 2][0] = r[0]; bf[np * 2][1] = r[1];
                bf[np * 2 + 1][0] = r[2]; bf[np * 2 + 1][1] = r[3];
            }
#pragma unroll
            for (int mi = 0; mi < 4; mi++)
#pragma unroll
                for (int ni = 0; ni < 4; ni++)
                    mma_bf16(acc[mi][ni], af[mi], bf[ni]);
        }
        __syncthreads();
    }

    // ---- epilogue: attn hi/lo into SMEM, then both-layout global writes ----
    unsigned short* th = (unsigned short*)(smem + 1024);
    unsigned short* tl = (unsigned short*)(smem + 1024 + 34816);   // 128*136*2
#pragma unroll
    for (int mi = 0; mi < 4; mi++) {
#pragma unroll
        for (int ni = 0; ni < 4; ni++) {
#pragma unroll
            for (int h = 0; h < 2; h++) {
                int row = m0w + mi * 16 + (lane >> 2) + h * 8;
                int col = n0w + ni * 8 + (lane & 3) * 2;
                float d0 = acc[mi][ni][h * 2];
                float d1 = acc[mi][ni][h * 2 + 1];
                float n1v = sn1[row];
                float e0 = fmaxf(n1v + sn2[col] - 2.f * d0, 0.f);
                float e1 = fmaxf(n1v + sn2[col + 1] - 2.f * d1, 0.f);
                float a0 = 1.f / (sqrtf(e0 + 1e-6f) + 1.f);
                float a1 = 1.f / (sqrtf(e1 + 1e-6f) + 1.f);
                __nv_bfloat16 h0 = __float2bfloat16(a0);
                __nv_bfloat16 h1 = __float2bfloat16(a1);
                __nv_bfloat16 l0 = __float2bfloat16(a0 - __bfloat162float(h0));
                __nv_bfloat16 l1 = __float2bfloat16(a1 - __bfloat162float(h1));
                uint32_t ph = (uint32_t)__bfloat16_as_ushort(h0) | ((uint32_t)__bfloat16_as_ushort(h1) << 16);
                uint32_t pl = (uint32_t)__bfloat16_as_ushort(l0) | ((uint32_t)__bfloat16_as_ushort(l1) << 16);
                *(uint32_t*)&th[row * 136 + col] = ph;
                *(uint32_t*)&tl[row * 136 + col] = pl;
            }
        }
    }
    __syncthreads();
    // pass 1: attnT[b][i][j] — contiguous in SMEM rows
    {
        int i_loc = t >> 1, jh = (t & 1) * 64;
        int gT = b * MAT + (i0 + i_loc) * SEQ + j0 + jh;
#pragma unroll
        for (int q = 0; q < 8; q++) {
            *(uint4*)&g_attnT_hi[gT + q * 8] = *(uint4*)&th[i_loc * 136 + jh + q * 8];
            *(uint4*)&g_attnT_lo[gT + q * 8] = *(uint4*)&tl[i_loc * 136 + jh + q * 8];
        }
    }
    // pass 2: attn[b][j][i] — transposed gather from SMEM
    {
        int j_loc = t >> 1, ih = (t & 1) * 64;
        int g = b * MAT + (j0 + j_loc) * SEQ + i0 + ih;
#pragma unroll
        for (int q = 0; q < 8; q++) {
            uint32_t wh[4], wl[4];
#pragma unroll
            for (int p = 0; p < 4; p++) {
                int r0 = ih + q * 8 + p * 2;
                wh[p] = (uint32_t)th[r0 * 136 + j_loc] | ((uint32_t)th[(r0 + 1) * 136 + j_loc] << 16);
                wl[p] = (uint32_t)tl[r0 * 136 + j_loc] | ((uint32_t)tl[(r0 + 1) * 136 + j_loc] << 16);
            }
            *(uint4*)&g_attn_hi[g + q * 8] = make_uint4(wh[0], wh[1], wh[2], wh[3]);
            *(uint4*)&g_attn_lo[g + q * 8] = make_uint4(wl[0], wl[1], wl[2], wl[3]);
        }
    }
}

// ---------------------------------------------------------------------------
// k_gemm2: split-bf16 HMMA  out = attn(.T) @ W^T + bias.
// 3 MMAs per fragment: Ahi*Whi + Ahi*Wlo + Alo*Whi.
// grid (2,2,32): z = b*2+which (0: x2_att ch3, 1: x1_att ch1)
// SMEM: [0,512) bias128; tiles at 1024: Ah,Al,Wh,Wl x 2 buffers.
// ---------------------------------------------------------------------------
#define G2_SMEM (1024 + 8 * TILE_B)   // 148480

__global__ void __launch_bounds__(256) k_gemm2(const float* __restrict__ bias) {
    extern __shared__ char smem[];
    uint32_t sb = smem_to_u32(smem);
    float* sbias = (float*)smem;
    int t = threadIdx.x, lane = t & 31, wid = t >> 5;
    int bz = blockIdx.z, b = bz >> 1, which = bz & 1;
    int o0 = blockIdx.x * 128, r0 = blockIdx.y * 128;
    int m0w = (wid & 1) * 64, n0w = (wid >> 1) * 32;

    const __nv_bfloat16* Ah = (which ? g_attnT_hi : g_attn_hi) + b * MAT + r0 * SEQ;
    const __nv_bfloat16* Al = (which ? g_attnT_lo : g_attn_lo) + b * MAT + r0 * SEQ;
    const __nv_bfloat16* Wh = g_Whi + o0 * SEQ;
    const __nv_bfloat16* Wl = g_Wlo + o0 * SEQ;
    if (t < 128) sbias[t] = bias[o0 + t];

    const uint32_t sAh = sb + 1024;
    const uint32_t sAl = sAh + 2 * TILE_B;
    const uint32_t sWh = sAl + 2 * TILE_B;
    const uint32_t sWl = sWh + 2 * TILE_B;

    auto load_chunk = [&](int kc, int buf) {
#pragma unroll
        for (int s = 0; s < 4; s++) {
            int seg = t + s * 256;
            int row = seg >> 3, c = seg & 7;
            uint32_t so = (uint32_t)(buf * TILE_B + row * TROW + c * 16);
            int go = row * SEQ + kc * 64 + c * 8;
            cp16(sAh + so, Ah + go);
            cp16(sAl + so, Al + go);
            cp16(sWh + so, Wh + go);
            cp16(sWl + so, Wl + go);
        }
    };

    float acc[4][4][4] = {};
    load_chunk(0, 0);
    CP_COMMIT();
    for (int kc = 0; kc < 4; kc++) {
        if (kc + 1 < 4) { load_chunk(kc + 1, (kc + 1) & 1); }
        CP_COMMIT();
        if (kc + 1 < 4) CP_WAIT1(); else CP_WAIT0();
        __syncthreads();
        uint32_t bo = (kc & 1) * TILE_B;
#pragma unroll
        for (int kk = 0; kk < 4; kk++) {
            uint32_t bh[4][2], bl[4][2];
#pragma unroll
            for (int np = 0; np < 2; np++) {
                uint32_t off = (uint32_t)((n0w + np * 16 + (lane & 7) + ((lane >> 4) & 1) * 8) * TROW
                                          + kk * 32 + ((lane >> 3) & 1) * 16);
                uint32_t r[4];
                ldsm4(r, sWh + bo + off);
                bh[np * 2][0] = r[0]; bh[np * 2][1] = r[1];
                bh[np * 2 + 1][0] = r[2]; bh[np * 2 + 1][1] = r[3];
                ldsm4(r, sWl + bo + off);
                bl[np * 2][0] = r[0]; bl[np * 2][1] = r[1];
                bl[np * 2 + 1][0] = r[2]; bl[np * 2 + 1][1] = r[3];
            }
#pragma unroll
            for (int mi = 0; mi < 4; mi++) {
                uint32_t off = (uint32_t)((m0w + mi * 16 + (lane & 15)) * TROW
                                          + kk * 32 + (lane >> 4) * 16);
                uint32_t ah[4], al[4];
                ldsm4(ah, sAh + bo + off);
                ldsm4(al, sAl + bo + off);
#pragma unroll
                for (int ni = 0; ni < 4; ni++) {
                    mma_bf16(acc[mi][ni], ah, bh[ni]);
                    mma_bf16(acc[mi][ni], ah, bl[ni]);
                    mma_bf16(acc[mi][ni], al, bh[ni]);
                }
            }
        }
        __syncthreads();
    }

    // ---- epilogue: bias add, fp32 store, BN channel stats ----
    float* out = which ? g_x1att : g_x2att;
    float ps = 0.f, pq = 0.f;
#pragma unroll
    for (int mi = 0; mi < 4; mi++) {
#pragma unroll
        for (int ni = 0; ni < 4; ni++) {
#pragma unroll
            for (int h = 0; h < 2; h++) {
                int row = r0 + m0w + mi * 16 + (lane >> 2) + h * 8;
                int colL = n0w + ni * 8 + (lane & 3) * 2;
                float v0 = acc[mi][ni][h * 2]     + sbias[colL];
                float v1 = acc[mi][ni][h * 2 + 1] + sbias[colL + 1];
                *(float2*)&out[b * MAT + row * DIM + o0 + colL] = make_float2(v0, v1);
                ps += v0 + v1;
                pq += v0 * v0 + v1 * v1;
            }
        }
    }
#pragma unroll
    for (int off = 16; off; off >>= 1) {
        ps += __shfl_xor_sync(0xffffffffu, ps, off);
        pq += __shfl_xor_sync(0xffffffffu, pq, off);
    }
    float* ws = (float*)(smem + 1024);
    float* wq = ws + 8;
    __syncthreads();
    if (lane == 0) { ws[wid] = ps; wq[wid] = pq; }
    __syncthreads();
    if (t == 0) {
        float S = 0.f, Q = 0.f;
#pragma unroll
        for (int w = 0; w < 8; w++) { S += ws[w]; Q += wq[w]; }
        int ch = which ? 1 : 3;
        atomicAdd(&g_sum[ch], S);
        atomicAdd(&g_sumsq[ch], Q);
    }
}

// ---------------------------------------------------------------------------
// k_bn: apply training-mode BN, write both outputs
// out layout: [which_out(2)][b(16)][c(2)][s(256)][d(256)]
// ---------------------------------------------------------------------------
__global__ void __launch_bounds__(256) k_bn(const float* __restrict__ x1,
                                            const float* __restrict__ x2,
                                            const float* __restrict__ gamma,
                                            const float* __restrict__ beta,
                                            float* __restrict__ out) {
    int idx = blockIdx.x * blockDim.x + threadIdx.x;
    int e = idx << 2;
    int which = e >> 21;
    int rem = e & ((1 << 21) - 1);
    int bb = rem >> 17;
    int c = (rem >> 16) & 1;
    int pos = rem & 65535;
    const float* src;
    int ch;
    if (which == 0) { src = c ? g_x1att : x1; ch = c ? 1 : 0; }
    else            { src = c ? g_x2att : x2; ch = c ? 3 : 2; }
    const float Ninv = 1.0f / (float)NTOT;
    float mean = g_sum[ch] * Ninv;
    float var = g_sumsq[ch] * Ninv - mean * mean;
    float sc = gamma[c] * rsqrtf(var + 1e-5f);
    float sh = beta[c] - mean * sc;
    float4 v = *(const float4*)&src[bb * MAT + pos];
    float4 o;
    o.x = v.x * sc + sh;
    o.y = v.y * sc + sh;
    o.z = v.z * sc + sh;
    o.w = v.w * sc + sh;
    *(float4*)&out[e] = o;
}

// ---------------------------------------------------------------------------
extern "C" void kernel_launch(void* const* d_in, const int* in_sizes, int n_in,
                              void* d_out, int out_size) {
    const float* x1    = (const float*)d_in[0];
    const float* x2    = (const float*)d_in[1];
    const float* W     = (const float*)d_in[2];
    const float* bias  = (const float*)d_in[3];
    const float* gamma = (const float*)d_in[4];
    const float* beta  = (const float*)d_in[5];
    float* out = (float*)d_out;

    static bool attr_set = false;
    if (!attr_set) {
        cudaFuncSetAttribute(k_gemm1, cudaFuncAttributeMaxDynamicSharedMemorySize, G1_SMEM);
        cudaFuncSetAttribute(k_gemm2, cudaFuncAttributeMaxDynamicSharedMemorySize, G2_SMEM);
        attr_set = true;
    }

    k_zero<<<1, 32>>>();
    k_prep<<<1088, 256>>>(x1, x2, W);
    k_gemm1<<<dim3(2, 2, 16), 256, G1_SMEM>>>();
    k_gemm2<<<dim3(2, 2, 32), 256, G2_SMEM>>>(bias);
    k_bn<<<4096, 256>>>(x1, x2, gamma, beta, out);
}

// round 4
// speedup vs baseline: 2.3856x; 1.3825x over previous
#include <cuda_runtime.h>
#include <cuda_fp16.h>
#include <stdint.h>

#define BATCH 16
#define SEQ 256
#define DIM 256
#define MAT 65536
#define NTOT 1048576
#define ABAR 0.042323627f   // 1/(1+sqrt(512))

// ---------------------------------------------------------------------------
// Device-global scratch
// ---------------------------------------------------------------------------
__device__ float g_x1att[NTOT];
__device__ float g_x2att[NTOT];
__device__ float g_n1[BATCH*SEQ];
__device__ float g_n2[BATCH*SEQ];
__device__ float g_sum[4];     // 0=x1, 1=x1_att, 2=x2, 3=x2_att
__device__ float g_sumsq[4];
__device__ float g_corr[DIM];  // ABAR*rowsum(W)+bias
__device__ __half g_x1h[NTOT];
__device__ __half g_x2h[NTOT];
__device__ __half g_Wh[SEQ*DIM];
__device__ __half g_d[NTOT];    // delta attn [b][j][i]
__device__ __half g_dT[NTOT];   // delta attn [b][i][j]

// ---------------------------------------------------------------------------
// Portable-ISA helpers (sm_80+)
// ---------------------------------------------------------------------------
__device__ __forceinline__ uint32_t smem_to_u32(const void* p) {
    uint32_t a;
    asm("{ .reg .u64 t; cvta.to.shared.u64 t, %1; cvt.u32.u64 %0, t; }" : "=r"(a) : "l"(p));
    return a;
}
__device__ __forceinline__ void ldsm4(uint32_t* r, uint32_t addr) {
    asm volatile("ldmatrix.sync.aligned.m8n8.x4.shared.b16 {%0,%1,%2,%3}, [%4];"
                 : "=r"(r[0]), "=r"(r[1]), "=r"(r[2]), "=r"(r[3]) : "r"(addr));
}
__device__ __forceinline__ void mma_fp16(float* c, const uint32_t* a, const uint32_t* b) {
    asm volatile("mma.sync.aligned.m16n8k16.row.col.f32.f16.f16.f32 "
                 "{%0,%1,%2,%3}, {%4,%5,%6,%7}, {%8,%9}, {%0,%1,%2,%3};"
                 : "+f"(c[0]), "+f"(c[1]), "+f"(c[2]), "+f"(c[3])
                 : "r"(a[0]), "r"(a[1]), "r"(a[2]), "r"(a[3]), "r"(b[0]), "r"(b[1]));
}
__device__ __forceinline__ void cp16(uint32_t saddr, const void* g) {
    asm volatile("cp.async.cg.shared.global [%0], [%1], 16;" :: "r"(saddr), "l"(g));
}
#define CP_COMMIT() asm volatile("cp.async.commit_group;" ::: "memory")
#define CP_WAIT1()  asm volatile("cp.async.wait_group 1;" ::: "memory")
#define CP_WAIT0()  asm volatile("cp.async.wait_group 0;" ::: "memory")

#define TROW 144                 // bytes per SMEM tile row (64 halfs + pad)
#define TILE128 (128 * TROW)     // 18432
#define TILE64  (64 * TROW)      // 9216

// ---------------------------------------------------------------------------
__global__ void k_zero() {
    int t = threadIdx.x;
    if (t < 4) { g_sum[t] = 0.f; g_sumsq[t] = 0.f; }
}

// ---------------------------------------------------------------------------
// k_prep: blocks [0,512) x1: norms+stats+fp16.  [512,1024) x2.
//         [1024,1088) W fp16 convert.  [1088,1120) corr = ABAR*rowsum(W)+bias
// ---------------------------------------------------------------------------
__global__ void __launch_bounds__(256) k_prep(const float* __restrict__ x1,
                                              const float* __restrict__ x2,
                                              const float* __restrict__ W,
                                              const float* __restrict__ bias) {
    int blk = blockIdx.x;
    int t = threadIdx.x;
    if (blk >= 1088) {   // corr rows
        int warp = t >> 5, lane = t & 31;
        int o = (blk - 1088) * 8 + warp;
        float s = 0.f;
#pragma unroll
        for (int c = 0; c < 8; c++) s += W[o * SEQ + lane + c * 32];
#pragma unroll
        for (int off = 16; off; off >>= 1) s += __shfl_xor_sync(0xffffffffu, s, off);
        if (lane == 0) g_corr[o] = ABAR * s + bias[o];
        return;
    }
    if (blk >= 1024) {   // W fp16
        int base = (blk - 1024) * 1024;
#pragma unroll
        for (int c = 0; c < 4; c++) {
            int i = base + c * 256 + t;
            g_Wh[i] = __float2half(W[i]);
        }
        return;
    }
    const float* X;
    float* Nrm;
    __half* Xh;
    int ch;
    if (blk < 512) { X = x1; Nrm = g_n1; Xh = g_x1h; ch = 0; }
    else           { X = x2; Nrm = g_n2; Xh = g_x2h; blk -= 512; ch = 2; }
    int warp = t >> 5, lane = t & 31;
    int row = blk * 8 + warp;
    const float* p = X + row * DIM;
    __half* ph = Xh + row * DIM;
    float s = 0.f, q = 0.f;
#pragma unroll
    for (int c = 0; c < 8; c++) {
        float v = p[lane + c * 32];
        s += v; q += v * v;
        ph[lane + c * 32] = __float2half(v);
    }
#pragma unroll
    for (int off = 16; off; off >>= 1) {
        s += __shfl_xor_sync(0xffffffffu, s, off);
        q += __shfl_xor_sync(0xffffffffu, q, off);
    }
    __shared__ float bs[8], bq[8];
    if (lane == 0) { Nrm[row] = q; bs[warp] = s; bq[warp] = q; }
    __syncthreads();
    if (t == 0) {
        float S = 0.f, Q = 0.f;
#pragma unroll
        for (int w = 0; w < 8; w++) { S += bs[w]; Q += bq[w]; }
        atomicAdd(&g_sum[ch], S);
        atomicAdd(&g_sumsq[ch], Q);
    }
}

// ---------------------------------------------------------------------------
// k_gemm1: fp16 HMMA  D[i][j] = x1_i . x2_j  (128x64 CTA tile, K=256)
// epilogue: delta = 1/(sqrt(max(n1+n2-2D,0)+1e-6)+1) - ABAR  -> fp16,
// written to g_dT [b][i][j] and g_d [b][j][i].
// grid (2,4,16): x->i-tile(128), y->j-tile(64), z->b. 256 threads, 8 warps
// (4x2), warp tile 32x32.
// SMEM: [0,512) sn1  [512,768) sn2  tiles@1024: A 2xTILE128, B 2xTILE64
//       epilogue: th ushort[128][72] @1024
// ---------------------------------------------------------------------------
#define G1_SMEM (1024 + 2 * TILE128 + 2 * TILE64)   // 56320

__global__ void __launch_bounds__(256) k_gemm1() {
    extern __shared__ char smem[];
    uint32_t sb = smem_to_u32(smem);
    float* sn1 = (float*)smem;
    float* sn2 = (float*)(smem + 512);
    int t = threadIdx.x, lane = t & 31, wid = t >> 5;
    int b = blockIdx.z, i0 = blockIdx.x * 128, j0 = blockIdx.y * 64;
    int m0w = (wid & 3) * 32, n0w = (wid >> 2) * 32;

    const __half* A = g_x1h + b * MAT + i0 * DIM;
    const __half* B = g_x2h + b * MAT + j0 * DIM;
    if (t < 128) sn1[t] = g_n1[b * SEQ + i0 + t];
    else if (t < 192) sn2[t - 128] = g_n2[b * SEQ + j0 + (t - 128)];

    const uint32_t sA = sb + 1024;
    const uint32_t sB = sA + 2 * TILE128;

    auto load_chunk = [&](int kc, int buf) {
#pragma unroll
        for (int s = 0; s < 4; s++) {        // A: 1024 cp16
            int seg = t + s * 256;
            int row = seg >> 3, c = seg & 7;
            cp16(sA + (uint32_t)(buf * TILE128 + row * TROW + c * 16),
                 A + row * DIM + kc * 64 + c * 8);
        }
#pragma unroll
        for (int s = 0; s < 2; s++) {        // B: 512 cp16
            int seg = t + s * 256;
            int row = seg >> 3, c = seg & 7;
            cp16(sB + (uint32_t)(buf * TILE64 + row * TROW + c * 16),
                 B + row * DIM + kc * 64 + c * 8);
        }
    };

    float acc[2][4][4] = {};
    load_chunk(0, 0);
    CP_COMMIT();
    for (int kc = 0; kc < 4; kc++) {
        if (kc + 1 < 4) load_chunk(kc + 1, (kc + 1) & 1);
        CP_COMMIT();
        if (kc + 1 < 4) CP_WAIT1(); else CP_WAIT0();
        __syncthreads();
        uint32_t bufA = sA + (kc & 1) * TILE128;
        uint32_t bufB = sB + (kc & 1) * TILE64;
#pragma unroll
        for (int kk = 0; kk < 4; kk++) {
            uint32_t af[2][4];
#pragma unroll
            for (int mi = 0; mi < 2; mi++)
                ldsm4(af[mi], bufA + (uint32_t)((m0w + mi * 16 + (lane & 15)) * TROW
                                                + kk * 32 + (lane >> 4) * 16));
            uint32_t bf[4][2];
#pragma unroll
            for (int np = 0; np < 2; np++) {
                uint32_t r[4];
                ldsm4(r, bufB + (uint32_t)((n0w + np * 16 + (lane & 7) + ((lane >> 4) & 1) * 8) * TROW
                                            + kk * 32 + ((lane >> 3) & 1) * 16));
                bf[np * 2][0] = r[0]; bf[np * 2][1] = r[1];
                bf[np * 2 + 1][0] = r[2]; bf[np * 2 + 1][1] = r[3];
            }
#pragma unroll
            for (int mi = 0; mi < 2; mi++)
#pragma unroll
                for (int ni = 0; ni < 4; ni++)
                    mma_fp16(acc[mi][ni], af[mi], bf[ni]);
        }
        __syncthreads();
    }

    // epilogue: delta fp16 into SMEM tile [128][72]
    unsigned short* th = (unsigned short*)(smem + 1024);
#pragma unroll
    for (int mi = 0; mi < 2; mi++) {
#pragma unroll
        for (int ni = 0; ni < 4; ni++) {
#pragma unroll
            for (int h = 0; h < 2; h++) {
                int row = m0w + mi * 16 + (lane >> 2) + h * 8;
                int col = n0w + ni * 8 + (lane & 3) * 2;
                float n1v = sn1[row];
                float e0 = fmaxf(n1v + sn2[col]     - 2.f * acc[mi][ni][h * 2],     0.f);
                float e1 = fmaxf(n1v + sn2[col + 1] - 2.f * acc[mi][ni][h * 2 + 1], 0.f);
                float a0 = 1.f / (sqrtf(e0 + 1e-6f) + 1.f) - ABAR;
                float a1 = 1.f / (sqrtf(e1 + 1e-6f) + 1.f) - ABAR;
                __half2 pk = __floats2half2_rn(a0, a1);
                *(__half2*)&th[row * 72 + col] = pk;
            }
        }
    }
    __syncthreads();
    // write g_dT [b][i][j]: contiguous rows of 64
    {
        int i = t >> 3, q = t & 7;
#pragma unroll
        for (int it = 0; it < 4; it++) {
            int ii = i + it * 32;
            *(uint4*)&g_dT[b * MAT + (i0 + ii) * SEQ + j0 + q * 8] =
                *(uint4*)&th[ii * 72 + q * 8];
        }
    }
    // write g_d [b][j][i]: transpose gather
#pragma unroll
    for (int it = 0; it < 4; it++) {
        int idx = t + it * 256;
        int j = idx >> 4, q = idx & 15;
        uint32_t w[4];
#pragma unroll
        for (int p = 0; p < 4; p++) {
            int r0 = q * 8 + p * 2;
            w[p] = (uint32_t)th[r0 * 72 + j] | ((uint32_t)th[(r0 + 1) * 72 + j] << 16);
        }
        *(uint4*)&g_d[b * MAT + (j0 + j) * SEQ + i0 + q * 8] = make_uint4(w[0], w[1], w[2], w[3]);
    }
}

// ---------------------------------------------------------------------------
// k_gemm2: fp16 HMMA  out = delta(.T) @ W^T + corr  (128x128 tile, K=256)
// grid (2,2,32): x->o-tile, y->r-tile, z=b*2+which (0: x2_att ch3, 1: x1_att ch1)
// 8 warps, warp tile 64x32. One MMA per fragment.
// SMEM: [0,512) corr, tiles@1024: A 2xTILE128, W 2xTILE128
// ---------------------------------------------------------------------------
#define G2_SMEM (1024 + 4 * TILE128)   // 74752

__global__ void __launch_bounds__(256) k_gemm2() {
    extern __shared__ char smem[];
    uint32_t sb = smem_to_u32(smem);
    float* scorr = (float*)smem;
    int t = threadIdx.x, lane = t & 31, wid = t >> 5;
    int bz = blockIdx.z, b = bz >> 1, which = bz & 1;
    int o0 = blockIdx.x * 128, r0 = blockIdx.y * 128;
    int m0w = (wid & 1) * 64, n0w = (wid >> 1) * 32;

    const __half* A = (which ? g_dT : g_d) + b * MAT + r0 * SEQ;
    const __half* Wp = g_Wh + o0 * SEQ;
    if (t < 128) scorr[t] = g_corr[o0 + t];

    const uint32_t sA = sb + 1024;
    const uint32_t sW = sA + 2 * TILE128;

    auto load_chunk = [&](int kc, int buf) {
#pragma unroll
        for (int s = 0; s < 4; s++) {
            int seg = t + s * 256;
            int row = seg >> 3, c = seg & 7;
            uint32_t so = (uint32_t)(buf * TILE128 + row * TROW + c * 16);
            int go = row * SEQ + kc * 64 + c * 8;
            cp16(sA + so, A + go);
            cp16(sW + so, Wp + go);
        }
    };

    float acc[4][4][4] = {};
    load_chunk(0, 0);
    CP_COMMIT();
    for (int kc = 0; kc < 4; kc++) {
        if (kc + 1 < 4) load_chunk(kc + 1, (kc + 1) & 1);
        CP_COMMIT();
        if (kc + 1 < 4) CP_WAIT1(); else CP_WAIT0();
        __syncthreads();
        uint32_t bufA = sA + (kc & 1) * TILE128;
        uint32_t bufW = sW + (kc & 1) * TILE128;
#pragma unroll
        for (int kk = 0; kk < 4; kk++) {
            uint32_t bf[4][2];
#pragma unroll
            for (int np = 0; np < 2; np++) {
                uint32_t r[4];
                ldsm4(r, bufW + (uint32_t)((n0w + np * 16 + (lane & 7) + ((lane >> 4) & 1) * 8) * TROW
                                            + kk * 32 + ((lane >> 3) & 1) * 16));
                bf[np * 2][0] = r[0]; bf[np * 2][1] = r[1];
                bf[np * 2 + 1][0] = r[2]; bf[np * 2 + 1][1] = r[3];
            }
#pragma unroll
            for (int mi = 0; mi < 4; mi++) {
                uint32_t af[4];
                ldsm4(af, bufA + (uint32_t)((m0w + mi * 16 + (lane & 15)) * TROW
                                             + kk * 32 + (lane >> 4) * 16));
#pragma unroll
                for (int ni = 0; ni < 4; ni++)
                    mma_fp16(acc[mi][ni], af, bf[ni]);
            }
        }
        __syncthreads();
    }

    // epilogue: +corr, fp32 store, BN stats
    float* out = which ? g_x1att : g_x2att;
    float ps = 0.f, pq = 0.f;
#pragma unroll
    for (int mi = 0; mi < 4; mi++) {
#pragma unroll
        for (int ni = 0; ni < 4; ni++) {
#pragma unroll
            for (int h = 0; h < 2; h++) {
                int row = r0 + m0w + mi * 16 + (lane >> 2) + h * 8;
                int colL = n0w + ni * 8 + (lane & 3) * 2;
                float v0 = acc[mi][ni][h * 2]     + scorr[colL];
                float v1 = acc[mi][ni][h * 2 + 1] + scorr[colL + 1];
                *(float2*)&out[b * MAT + row * DIM + o0 + colL] = make_float2(v0, v1);
                ps += v0 + v1;
                pq += v0 * v0 + v1 * v1;
            }
        }
    }
#pragma unroll
    for (int off = 16; off; off >>= 1) {
        ps += __shfl_xor_sync(0xffffffffu, ps, off);
        pq += __shfl_xor_sync(0xffffffffu, pq, off);
    }
    float* ws = (float*)(smem + 1024);
    float* wq = ws + 8;
    __syncthreads();
    if (lane == 0) { ws[wid] = ps; wq[wid] = pq; }
    __syncthreads();
    if (t == 0) {
        float S = 0.f, Q = 0.f;
#pragma unroll
        for (int w = 0; w < 8; w++) { S += ws[w]; Q += wq[w]; }
        int ch = which ? 1 : 3;
        atomicAdd(&g_sum[ch], S);
        atomicAdd(&g_sumsq[ch], Q);
    }
}

// ---------------------------------------------------------------------------
// k_bn: apply training-mode BN, write both outputs
// out layout: [which_out(2)][b(16)][c(2)][s(256)][d(256)]
// ---------------------------------------------------------------------------
__global__ void __launch_bounds__(256) k_bn(const float* __restrict__ x1,
                                            const float* __restrict__ x2,
                                            const float* __restrict__ gamma,
                                            const float* __restrict__ beta,
                                            float* __restrict__ out) {
    int idx = blockIdx.x * blockDim.x + threadIdx.x;
    int e = idx << 2;
    int which = e >> 21;
    int rem = e & ((1 << 21) - 1);
    int bb = rem >> 17;
    int c = (rem >> 16) & 1;
    int pos = rem & 65535;
    const float* src;
    int ch;
    if (which == 0) { src = c ? g_x1att : x1; ch = c ? 1 : 0; }
    else            { src = c ? g_x2att : x2; ch = c ? 3 : 2; }
    const float Ninv = 1.0f / (float)NTOT;
    float mean = g_sum[ch] * Ninv;
    float var = g_sumsq[ch] * Ninv - mean * mean;
    float sc = gamma[c] * rsqrtf(var + 1e-5f);
    float sh = beta[c] - mean * sc;
    float4 v = *(const float4*)&src[bb * MAT + pos];
    float4 o;
    o.x = v.x * sc + sh;
    o.y = v.y * sc + sh;
    o.z = v.z * sc + sh;
    o.w = v.w * sc + sh;
    *(float4*)&out[e] = o;
}

// ---------------------------------------------------------------------------
extern "C" void kernel_launch(void* const* d_in, const int* in_sizes, int n_in,
                              void* d_out, int out_size) {
    const float* x1    = (const float*)d_in[0];
    const float* x2    = (const float*)d_in[1];
    const float* W     = (const float*)d_in[2];
    const float* bias  = (const float*)d_in[3];
    const float* gamma = (const float*)d_in[4];
    const float* beta  = (const float*)d_in[5];
    float* out = (float*)d_out;

    static bool attr_set = false;
    if (!attr_set) {
        cudaFuncSetAttribute(k_gemm1, cudaFuncAttributeMaxDynamicSharedMemorySize, G1_SMEM);
        cudaFuncSetAttribute(k_gemm2, cudaFuncAttributeMaxDynamicSharedMemorySize, G2_SMEM);
        attr_set = true;
    }

    k_zero<<<1, 32>>>();
    k_prep<<<1120, 256>>>(x1, x2, W, bias);
    k_gemm1<<<dim3(2, 4, 16), 256, G1_SMEM>>>();
    k_gemm2<<<dim3(2, 2, 32), 256, G2_SMEM>>>();
    k_bn<<<4096, 256>>>(x1, x2, gamma, beta, out);
}

// round 5
// speedup vs baseline: 2.4894x; 1.0435x over previous
#include <cuda_runtime.h>
#include <cuda_fp16.h>
#include <stdint.h>

#define BATCH 16
#define SEQ 256
#define DIM 256
#define MAT 65536
#define NTOT 1048576
#define ABAR 0.042323627f   // 1/(1+sqrt(512))

// ---------------------------------------------------------------------------
// Device-global scratch
// ---------------------------------------------------------------------------
__device__ float g_x1att[NTOT];
__device__ float g_x2att[NTOT];
__device__ float g_n1[BATCH*SEQ];
__device__ float g_n2[BATCH*SEQ];
__device__ float g_sum[4];     // 0=x1, 1=x1_att, 2=x2, 3=x2_att
__device__ float g_sumsq[4];
__device__ float g_corr[DIM];  // ABAR*rowsum(W)+bias
__device__ __half g_x1h[NTOT];
__device__ __half g_x2h[NTOT];
__device__ __half g_Wh[SEQ*DIM];
__device__ __half g_d[NTOT];    // delta attn [b][j][i]
__device__ __half g_dT[NTOT];   // delta attn [b][i][j]

// ---------------------------------------------------------------------------
// Portable-ISA helpers (sm_80+)
// ---------------------------------------------------------------------------
__device__ __forceinline__ uint32_t smem_to_u32(const void* p) {
    uint32_t a;
    asm("{ .reg .u64 t; cvta.to.shared.u64 t, %1; cvt.u32.u64 %0, t; }" : "=r"(a) : "l"(p));
    return a;
}
__device__ __forceinline__ void ldsm4(uint32_t* r, uint32_t addr) {
    asm volatile("ldmatrix.sync.aligned.m8n8.x4.shared.b16 {%0,%1,%2,%3}, [%4];"
                 : "=r"(r[0]), "=r"(r[1]), "=r"(r[2]), "=r"(r[3]) : "r"(addr));
}
__device__ __forceinline__ void mma_fp16(float* c, const uint32_t* a, const uint32_t* b) {
    asm volatile("mma.sync.aligned.m16n8k16.row.col.f32.f16.f16.f32 "
                 "{%0,%1,%2,%3}, {%4,%5,%6,%7}, {%8,%9}, {%0,%1,%2,%3};"
                 : "+f"(c[0]), "+f"(c[1]), "+f"(c[2]), "+f"(c[3])
                 : "r"(a[0]), "r"(a[1]), "r"(a[2]), "r"(a[3]), "r"(b[0]), "r"(b[1]));
}
__device__ __forceinline__ void cp16(uint32_t saddr, const void* g) {
    asm volatile("cp.async.cg.shared.global [%0], [%1], 16;" :: "r"(saddr), "l"(g));
}
#define CP_COMMIT() asm volatile("cp.async.commit_group;" ::: "memory")
#define CP_WAIT1()  asm volatile("cp.async.wait_group 1;" ::: "memory")
#define CP_WAIT0()  asm volatile("cp.async.wait_group 0;" ::: "memory")

#define TROW 144                 // bytes per SMEM tile row (64 halfs + pad)
#define TILE64  (64 * TROW)      // 9216

// ---------------------------------------------------------------------------
__global__ void k_zero() {
    int t = threadIdx.x;
    if (t < 4) { g_sum[t] = 0.f; g_sumsq[t] = 0.f; }
}

// ---------------------------------------------------------------------------
// k_prep: blocks [0,512) x1: norms+stats+fp16.  [512,1024) x2.
//         [1024,1088) W fp16 convert.  [1088,1120) corr = ABAR*rowsum(W)+bias
// ---------------------------------------------------------------------------
__global__ void __launch_bounds__(256) k_prep(const float* __restrict__ x1,
                                              const float* __restrict__ x2,
                                              const float* __restrict__ W,
                                              const float* __restrict__ bias) {
    int blk = blockIdx.x;
    int t = threadIdx.x;
    if (blk >= 1088) {   // corr rows
        int warp = t >> 5, lane = t & 31;
        int o = (blk - 1088) * 8 + warp;
        float s = 0.f;
#pragma unroll
        for (int c = 0; c < 8; c++) s += W[o * SEQ + lane + c * 32];
#pragma unroll
        for (int off = 16; off; off >>= 1) s += __shfl_xor_sync(0xffffffffu, s, off);
        if (lane == 0) g_corr[o] = ABAR * s + bias[o];
        return;
    }
    if (blk >= 1024) {   // W fp16
        int base = (blk - 1024) * 1024;
#pragma unroll
        for (int c = 0; c < 4; c++) {
            int i = base + c * 256 + t;
            g_Wh[i] = __float2half(W[i]);
        }
        return;
    }
    const float* X;
    float* Nrm;
    __half* Xh;
    int ch;
    if (blk < 512) { X = x1; Nrm = g_n1; Xh = g_x1h; ch = 0; }
    else           { X = x2; Nrm = g_n2; Xh = g_x2h; blk -= 512; ch = 2; }
    int warp = t >> 5, lane = t & 31;
    int row = blk * 8 + warp;
    const float* p = X + row * DIM;
    __half* ph = Xh + row * DIM;
    float s = 0.f, q = 0.f;
#pragma unroll
    for (int c = 0; c < 8; c++) {
        float v = p[lane + c * 32];
        s += v; q += v * v;
        ph[lane + c * 32] = __float2half(v);
    }
#pragma unroll
    for (int off = 16; off; off >>= 1) {
        s += __shfl_xor_sync(0xffffffffu, s, off);
        q += __shfl_xor_sync(0xffffffffu, q, off);
    }
    __shared__ float bs[8], bq[8];
    if (lane == 0) { Nrm[row] = q; bs[warp] = s; bq[warp] = q; }
    __syncthreads();
    if (t == 0) {
        float S = 0.f, Q = 0.f;
#pragma unroll
        for (int w = 0; w < 8; w++) { S += bs[w]; Q += bq[w]; }
        atomicAdd(&g_sum[ch], S);
        atomicAdd(&g_sumsq[ch], Q);
    }
}

// ---------------------------------------------------------------------------
// k_gemm1: fp16 HMMA  D[i][j] = x1_i . x2_j  (64x64 CTA tile, K=256)
// epilogue: delta = 1/(sqrt(max(n1+n2-2D,0)+1e-6)+1) - ABAR  -> fp16 ->
// g_dT [b][i][j] and g_d [b][j][i].
// grid (4,4,16), 128 threads, 4 warps (2x2), warp tile 32x32.
// SMEM: [0,256) sn1  [256,512) sn2  tiles@1024: A 2xTILE64, B 2xTILE64
//       epilogue: th ushort[64][72] @1024
// ---------------------------------------------------------------------------
#define G1_SMEM (1024 + 4 * TILE64)   // 37888

__global__ void __launch_bounds__(128) k_gemm1() {
    extern __shared__ char smem[];
    uint32_t sb = smem_to_u32(smem);
    float* sn1 = (float*)smem;
    float* sn2 = (float*)(smem + 256);
    int t = threadIdx.x, lane = t & 31, wid = t >> 5;
    int b = blockIdx.z, i0 = blockIdx.x * 64, j0 = blockIdx.y * 64;
    int m0w = (wid & 1) * 32, n0w = (wid >> 1) * 32;

    const __half* A = g_x1h + b * MAT + i0 * DIM;
    const __half* B = g_x2h + b * MAT + j0 * DIM;
    if (t < 64)       sn1[t]      = g_n1[b * SEQ + i0 + t];
    else              sn2[t - 64] = g_n2[b * SEQ + j0 + (t - 64)];

    const uint32_t sA = sb + 1024;
    const uint32_t sB = sA + 2 * TILE64;

    auto load_chunk = [&](int kc, int buf) {
#pragma unroll
        for (int s = 0; s < 4; s++) {        // 512 cp16 each operand
            int seg = t + s * 128;
            int row = seg >> 3, c = seg & 7;
            uint32_t so = (uint32_t)(buf * TILE64 + row * TROW + c * 16);
            cp16(sA + so, A + row * DIM + kc * 64 + c * 8);
            cp16(sB + so, B + row * DIM + kc * 64 + c * 8);
        }
    };

    float acc[2][4][4] = {};
    load_chunk(0, 0);
    CP_COMMIT();
    for (int kc = 0; kc < 4; kc++) {
        if (kc + 1 < 4) load_chunk(kc + 1, (kc + 1) & 1);
        CP_COMMIT();
        if (kc + 1 < 4) CP_WAIT1(); else CP_WAIT0();
        __syncthreads();
        uint32_t bufA = sA + (kc & 1) * TILE64;
        uint32_t bufB = sB + (kc & 1) * TILE64;
#pragma unroll
        for (int kk = 0; kk < 4; kk++) {
            uint32_t af[2][4];
#pragma unroll
            for (int mi = 0; mi < 2; mi++)
                ldsm4(af[mi], bufA + (uint32_t)((m0w + mi * 16 + (lane & 15)) * TROW
                                                + kk * 32 + (lane >> 4) * 16));
            uint32_t bf[4][2];
#pragma unroll
            for (int np = 0; np < 2; np++) {
                uint32_t r[4];
                ldsm4(r, bufB + (uint32_t)((n0w + np * 16 + (lane & 7) + ((lane >> 4) & 1) * 8) * TROW
                                            + kk * 32 + ((lane >> 3) & 1) * 16));
                bf[np * 2][0] = r[0]; bf[np * 2][1] = r[1];
                bf[np * 2 + 1][0] = r[2]; bf[np * 2 + 1][1] = r[3];
            }
#pragma unroll
            for (int mi = 0; mi < 2; mi++)
#pragma unroll
                for (int ni = 0; ni < 4; ni++)
                    mma_fp16(acc[mi][ni], af[mi], bf[ni]);
        }
        __syncthreads();
    }

    // epilogue: delta fp16 into SMEM tile [64][72]
    unsigned short* th = (unsigned short*)(smem + 1024);
#pragma unroll
    for (int mi = 0; mi < 2; mi++) {
#pragma unroll
        for (int ni = 0; ni < 4; ni++) {
#pragma unroll
            for (int h = 0; h < 2; h++) {
                int row = m0w + mi * 16 + (lane >> 2) + h * 8;
                int col = n0w + ni * 8 + (lane & 3) * 2;
                float n1v = sn1[row];
                float e0 = fmaxf(n1v + sn2[col]     - 2.f * acc[mi][ni][h * 2],     0.f);
                float e1 = fmaxf(n1v + sn2[col + 1] - 2.f * acc[mi][ni][h * 2 + 1], 0.f);
                float a0 = 1.f / (sqrtf(e0 + 1e-6f) + 1.f) - ABAR;
                float a1 = 1.f / (sqrtf(e1 + 1e-6f) + 1.f) - ABAR;
                __half2 pk = __floats2half2_rn(a0, a1);
                *(__half2*)&th[row * 72 + col] = pk;
            }
        }
    }
    __syncthreads();
    // g_dT [b][i][j]: contiguous rows
    {
        int i = t >> 1, qh = (t & 1) * 32;
        int gT = b * MAT + (i0 + i) * SEQ + j0 + qh;
#pragma unroll
        for (int p = 0; p < 4; p++)
            *(uint4*)&g_dT[gT + p * 8] = *(uint4*)&th[i * 72 + qh + p * 8];
    }
    // g_d [b][j][i]: transpose gather
    {
        int j = t >> 1, ih = (t & 1) * 32;
        int g = b * MAT + (j0 + j) * SEQ + i0 + ih;
#pragma unroll
        for (int p = 0; p < 4; p++) {
            uint32_t w[4];
#pragma unroll
            for (int pp = 0; pp < 4; pp++) {
                int r0 = ih + p * 8 + pp * 2;
                w[pp] = (uint32_t)th[r0 * 72 + j] | ((uint32_t)th[(r0 + 1) * 72 + j] << 16);
            }
            *(uint4*)&g_d[g + p * 8] = make_uint4(w[0], w[1], w[2], w[3]);
        }
    }
}

// ---------------------------------------------------------------------------
// k_gemm2: fp16 HMMA  out = delta(.T) @ W^T + corr  (64x64 tile, K=256)
// grid (4,4,32): x->o-tile, y->r-tile, z=b*2+which (0: x2_att ch3, 1: x1_att ch1)
// 128 threads, 4 warps (2x2), warp tile 32x32.
// SMEM: [0,256) corr, tiles@1024: A 2xTILE64, W 2xTILE64
// ---------------------------------------------------------------------------
#define G2_SMEM (1024 + 4 * TILE64)   // 37888

__global__ void __launch_bounds__(128) k_gemm2() {
    extern __shared__ char smem[];
    uint32_t sb = smem_to_u32(smem);
    float* scorr = (float*)smem;
    int t = threadIdx.x, lane = t & 31, wid = t >> 5;
    int bz = blockIdx.z, b = bz >> 1, which = bz & 1;
    int o0 = blockIdx.x * 64, r0 = blockIdx.y * 64;
    int m0w = (wid & 1) * 32, n0w = (wid >> 1) * 32;

    const __half* A = (which ? g_dT : g_d) + b * MAT + r0 * SEQ;
    const __half* Wp = g_Wh + o0 * SEQ;
    if (t < 64) scorr[t] = g_corr[o0 + t];

    const uint32_t sA = sb + 1024;
    const uint32_t sW = sA + 2 * TILE64;

    auto load_chunk = [&](int kc, int buf) {
#pragma unroll
        for (int s = 0; s < 4; s++) {
            int seg = t + s * 128;
            int row = seg >> 3, c = seg & 7;
            uint32_t so = (uint32_t)(buf * TILE64 + row * TROW + c * 16);
            int go = row * SEQ + kc * 64 + c * 8;
            cp16(sA + so, A + go);
            cp16(sW + so, Wp + go);
        }
    };

    float acc[2][4][4] = {};
    load_chunk(0, 0);
    CP_COMMIT();
    for (int kc = 0; kc < 4; kc++) {
        if (kc + 1 < 4) load_chunk(kc + 1, (kc + 1) & 1);
        CP_COMMIT();
        if (kc + 1 < 4) CP_WAIT1(); else CP_WAIT0();
        __syncthreads();
        uint32_t bufA = sA + (kc & 1) * TILE64;
        uint32_t bufW = sW + (kc & 1) * TILE64;
#pragma unroll
        for (int kk = 0; kk < 4; kk++) {
            uint32_t bf[4][2];
#pragma unroll
            for (int np = 0; np < 2; np++) {
                uint32_t r[4];
                ldsm4(r, bufW + (uint32_t)((n0w + np * 16 + (lane & 7) + ((lane >> 4) & 1) * 8) * TROW
                                            + kk * 32 + ((lane >> 3) & 1) * 16));
                bf[np * 2][0] = r[0]; bf[np * 2][1] = r[1];
                bf[np * 2 + 1][0] = r[2]; bf[np * 2 + 1][1] = r[3];
            }
#pragma unroll
            for (int mi = 0; mi < 2; mi++) {
                uint32_t af[4];
                ldsm4(af, bufA + (uint32_t)((m0w + mi * 16 + (lane & 15)) * TROW
                                             + kk * 32 + (lane >> 4) * 16));
#pragma unroll
                for (int ni = 0; ni < 4; ni++)
                    mma_fp16(acc[mi][ni], af, bf[ni]);
            }
        }
        __syncthreads();
    }

    // epilogue: +corr, fp32 store, BN stats
    float* out = which ? g_x1att : g_x2att;
    float ps = 0.f, pq = 0.f;
#pragma unroll
    for (int mi = 0; mi < 2; mi++) {
#pragma unroll
        for (int ni = 0; ni < 4; ni++) {
#pragma unroll
            for (int h = 0; h < 2; h++) {
                int row = r0 + m0w + mi * 16 + (lane >> 2) + h * 8;
                int colL = n0w + ni * 8 + (lane & 3) * 2;
                float v0 = acc[mi][ni][h * 2]     + scorr[colL];
                float v1 = acc[mi][ni][h * 2 + 1] + scorr[colL + 1];
                *(float2*)&out[b * MAT + row * DIM + o0 + colL] = make_float2(v0, v1);
                ps += v0 + v1;
                pq += v0 * v0 + v1 * v1;
            }
        }
    }
#pragma unroll
    for (int off = 16; off; off >>= 1) {
        ps += __shfl_xor_sync(0xffffffffu, ps, off);
        pq += __shfl_xor_sync(0xffffffffu, pq, off);
    }
    float* ws = (float*)(smem + 256);
    float* wq = ws + 4;
    __syncthreads();
    if (lane == 0) { ws[wid] = ps; wq[wid] = pq; }
    __syncthreads();
    if (t == 0) {
        float S = ws[0] + ws[1] + ws[2] + ws[3];
        float Q = wq[0] + wq[1] + wq[2] + wq[3];
        int ch = which ? 1 : 3;
        atomicAdd(&g_sum[ch], S);
        atomicAdd(&g_sumsq[ch], Q);
    }
}

// ---------------------------------------------------------------------------
// k_bn: apply training-mode BN, write both outputs
// out layout: [which_out(2)][b(16)][c(2)][s(256)][d(256)]
// ---------------------------------------------------------------------------
__global__ void __launch_bounds__(256) k_bn(const float* __restrict__ x1,
                                            const float* __restrict__ x2,
                                            const float* __restrict__ gamma,
                                            const float* __restrict__ beta,
                                            float* __restrict__ out) {
    int idx = blockIdx.x * blockDim.x + threadIdx.x;
    int e = idx << 2;
    int which = e >> 21;
    int rem = e & ((1 << 21) - 1);
    int bb = rem >> 17;
    int c = (rem >> 16) & 1;
    int pos = rem & 65535;
    const float* src;
    int ch;
    if (which == 0) { src = c ? g_x1att : x1; ch = c ? 1 : 0; }
    else            { src = c ? g_x2att : x2; ch = c ? 3 : 2; }
    const float Ninv = 1.0f / (float)NTOT;
    float mean = g_sum[ch] * Ninv;
    float var = g_sumsq[ch] * Ninv - mean * mean;
    float sc = gamma[c] * rsqrtf(var + 1e-5f);
    float sh = beta[c] - mean * sc;
    float4 v = *(const float4*)&src[bb * MAT + pos];
    float4 o;
    o.x = v.x * sc + sh;
    o.y = v.y * sc + sh;
    o.z = v.z * sc + sh;
    o.w = v.w * sc + sh;
    *(float4*)&out[e] = o;
}

// ---------------------------------------------------------------------------
extern "C" void kernel_launch(void* const* d_in, const int* in_sizes, int n_in,
                              void* d_out, int out_size) {
    const float* x1    = (const float*)d_in[0];
    const float* x2    = (const float*)d_in[1];
    const float* W     = (const float*)d_in[2];
    const float* bias  = (const float*)d_in[3];
    const float* gamma = (const float*)d_in[4];
    const float* beta  = (const float*)d_in[5];
    float* out = (float*)d_out;

    k_zero<<<1, 32>>>();
    k_prep<<<1120, 256>>>(x1, x2, W, bias);
    k_gemm1<<<dim3(4, 4, 16), 128, G1_SMEM>>>();
    k_gemm2<<<dim3(4, 4, 32), 128, G2_SMEM>>>();
    k_bn<<<4096, 256>>>(x1, x2, gamma, beta, out);
}